// round 15
// baseline (speedup 1.0000x reference)
#include <cuda_runtime.h>
#include <cuda_fp16.h>
#include <cstdint>

#define NN      50000
#define EE      800000
#define KDIM    128
#define OUTDIM  64

typedef unsigned long long u64;
typedef unsigned int u32;

// ---------------- device scratch ----------------
__device__ __half g_bufH1[NN * KDIM];    // g1 = x@W1 ; later g2 = A*h1
__device__ __half g_bufH2[NN * KDIM];    // h1 = relu(A*g1 + b1)
__device__ __half g_W1t[KDIM * KDIM];    // W1^T fp16 [n][k]
__device__ __half g_W2t[KDIM * KDIM];    // W2^T fp16 [n][k]
__device__ __half g_Wct[OUTDIM * KDIM];  // (W3@W4)^T fp16 [n][k]
__device__ float  g_bc[OUTDIM];          // b3@W4 + b4
__device__ int    g_cnt[NN];
__device__ int    g_rowptr[NN + 1];
__device__ int    g_cursor[NN];
__device__ int    g_adj[EE];
__device__ float  g_invdeg[NN];
__device__ int    g_is64;
__device__ int    g_bsum[512];
__device__ int    g_done;

// ---------------- mma helper ----------------
__device__ __forceinline__ void mma16816(float* c, const u32* a, const u32* b) {
    asm volatile(
        "mma.sync.aligned.m16n8k16.row.col.f32.f16.f16.f32 "
        "{%0,%1,%2,%3}, {%4,%5,%6,%7}, {%8,%9}, {%0,%1,%2,%3};"
        : "+f"(c[0]), "+f"(c[1]), "+f"(c[2]), "+f"(c[3])
        : "r"(a[0]), "r"(a[1]), "r"(a[2]), "r"(a[3]), "r"(b[0]), "r"(b[1]));
}

// ---------------- prep_w: W1t/W2t fp16 transposed ----------------
__global__ void prep_w_kernel(const float* __restrict__ W1,
                              const float* __restrict__ W2) {
    int b = blockIdx.x, t = threadIdx.x;   // 256 blocks x 128
    if (b < 128) {
        g_W1t[t * KDIM + b] = __float2half(W1[b * KDIM + t]);
    } else {
        int k = b - 128;
        g_W2t[t * KDIM + k] = __float2half(W2[k * KDIM + t]);
    }
}

// ---------------- prep_wc: Wct fp16 + bc; resets g_done ----------------
__global__ void prep_wc_kernel(const float* __restrict__ W3, const float* __restrict__ b3,
                               const float* __restrict__ W4, const float* __restrict__ b4) {
    int n = blockIdx.x, t = threadIdx.x;   // 64 blocks x 128
    if (n == 0 && t == 0) g_done = 0;
    float s = 0.0f;
    for (int m = 0; m < KDIM; m++)
        s += W3[t * KDIM + m] * W4[m * OUTDIM + n];
    g_Wct[n * KDIM + t] = __float2half(s);
    if (t == 0) {
        float sb = b4[n];
        for (int m = 0; m < KDIM; m++)
            sb += b3[m] * W4[m * OUTDIM + n];
        g_bc[n] = sb;
    }
}

// ---------------- resident-grid spin barrier ----------------
__device__ __forceinline__ void gridbar(int target) {
    __syncthreads();
    if (threadIdx.x == 0) {
        __threadfence();
        atomicAdd(&g_done, 1);
        while (*(volatile int*)&g_done < target) { }
    }
    __syncthreads();
}

// ---------------- single persistent CSR build: 444 blocks (3 CTA/SM resident) ----------------
__global__ void __launch_bounds__(512, 3)
csr_all_kernel(const int* __restrict__ ei, int E, int M, int NB) {
    __shared__ int sh[512];
    int b = blockIdx.x, t = threadIdx.x;
    int gstride = NB * 512;

    for (int i = b * 512 + t; i < M; i += gstride) g_cnt[i] = 0;
    if (b == 0 && t == 0) {
        int allz = 1;
        for (int e = 0; e < 64; e++) {
            if (ei[2 * e + 1] != 0) { allz = 0; break; }
        }
        g_is64 = allz;
    }
    gridbar(NB);
    int is64 = g_is64;

    // phase 1: count, 4-way batched loads (MLP=4)
    {
        int e = b * 512 + t;
        for (; e + 3 * gstride < E; e += 4 * gstride) {
            int e1 = e + gstride, e2 = e + 2 * gstride, e3 = e + 3 * gstride;
            int r0 = is64 ? ei[2 * e]  : ei[e];
            int r1 = is64 ? ei[2 * e1] : ei[e1];
            int r2 = is64 ? ei[2 * e2] : ei[e2];
            int r3 = is64 ? ei[2 * e3] : ei[e3];
            atomicAdd(&g_cnt[r0], 1);
            atomicAdd(&g_cnt[r1], 1);
            atomicAdd(&g_cnt[r2], 1);
            atomicAdd(&g_cnt[r3], 1);
        }
        for (; e < E; e += gstride) {
            int r = is64 ? ei[2 * e] : ei[e];
            atomicAdd(&g_cnt[r], 1);
        }
    }
    gridbar(2 * NB);

    int CH = (M + NB - 1) / NB;          // 113 for NB=444
    int lo = b * CH;
    int hi = lo + CH; if (hi > M) hi = M;
    {
        int s = 0;
        for (int i = lo + t; i < hi; i += 512) s += __ldcg(&g_cnt[i]);
        sh[t] = s; __syncthreads();
        for (int d = 256; d > 0; d >>= 1) {
            if (t < d) sh[t] += sh[t + d];
            __syncthreads();
        }
        if (t == 0) g_bsum[b] = sh[0];
    }
    gridbar(3 * NB);

    // every block scans all NB (<=512) chunk sums
    int boff, total;
    {
        int v = (t < NB) ? __ldcg(&g_bsum[t]) : 0;
        sh[t] = v;
        __syncthreads();
        for (int d = 1; d < 512; d <<= 1) {
            int u = (t >= d) ? sh[t - d] : 0;
            __syncthreads();
            sh[t] += u;
            __syncthreads();
        }
        total = sh[NB - 1];
        boff  = (b > 0) ? sh[b - 1] : 0;
        __syncthreads();
    }

    // emit rowptr/cursor/invdeg for this chunk (CH <= 512, thread t = row lo+t)
    {
        int row = lo + t;
        int v = (t < CH && row < M) ? __ldcg(&g_cnt[row]) : 0;
        sh[t] = v; __syncthreads();
        for (int d = 1; d < 512; d <<= 1) {
            int u = (t >= d) ? sh[t - d] : 0;
            __syncthreads();
            sh[t] += u;
            __syncthreads();
        }
        int ex = boff + sh[t] - v;
        if (t < CH && row < M) {
            g_rowptr[row] = ex;
            g_cursor[row] = ex;
            g_invdeg[row] = 1.0f / (float)(v + 1);
        }
        if (b == 0 && t == 0) g_rowptr[M] = total;
    }
    gridbar(4 * NB);

    // phase 4: fill, 4-way batched
    {
        int e = b * 512 + t;
        for (; e + 3 * gstride < E; e += 4 * gstride) {
            int e1 = e + gstride, e2 = e + 2 * gstride, e3 = e + 3 * gstride;
            int r0, c0, r1, c1, r2, c2, r3, c3;
            if (is64) {
                r0 = ei[2 * e];  c0 = ei[2 * E + 2 * e];
                r1 = ei[2 * e1]; c1 = ei[2 * E + 2 * e1];
                r2 = ei[2 * e2]; c2 = ei[2 * E + 2 * e2];
                r3 = ei[2 * e3]; c3 = ei[2 * E + 2 * e3];
            } else {
                r0 = ei[e];  c0 = ei[E + e];
                r1 = ei[e1]; c1 = ei[E + e1];
                r2 = ei[e2]; c2 = ei[E + e2];
                r3 = ei[e3]; c3 = ei[E + e3];
            }
            int p0 = atomicAdd(&g_cursor[r0], 1);
            int p1 = atomicAdd(&g_cursor[r1], 1);
            int p2 = atomicAdd(&g_cursor[r2], 1);
            int p3 = atomicAdd(&g_cursor[r3], 1);
            g_adj[p0] = c0;
            g_adj[p1] = c1;
            g_adj[p2] = c2;
            g_adj[p3] = c3;
        }
        for (; e < E; e += gstride) {
            int r, c;
            if (is64) { r = ei[2 * e]; c = ei[2 * E + 2 * e]; }
            else      { r = ei[e];     c = ei[E + e]; }
            int p = atomicAdd(&g_cursor[r], 1);
            g_adj[p] = c;
        }
    }
}

// ---------------- SpMM: two-stage 8-edge fp16 tree, <=32 regs (proven R14) ----------------
template <bool BR, bool HOUT>
__global__ void __launch_bounds__(256, 8)
spmm_h_kernel(const __half* __restrict__ src,
              const float* __restrict__ bias,
              void* __restrict__ dstv, int M) {
    int warp = (blockIdx.x * blockDim.x + threadIdx.x) >> 5;
    if (warp >= M) return;
    int lane = threadIdx.x & 31;

    const uint2* s2 = (const uint2*)src;
    size_t rowbase = (size_t)warp * 32;

    float ax, ay, az, aw;
    {
        uint2 u = s2[rowbase + lane];
        float2 f0 = __half22float2(*(__half2*)&u.x);
        float2 f1 = __half22float2(*(__half2*)&u.y);
        ax = f0.x; ay = f0.y; az = f1.x; aw = f1.y;
    }

    int e   = g_rowptr[warp];
    int end = g_rowptr[warp + 1];

    for (; e + 8 <= end; e += 8) {
        __half2 px, py;
        {
            int j0 = g_adj[e],     j1 = g_adj[e + 1];
            int j2 = g_adj[e + 2], j3 = g_adj[e + 3];
            uint2 v0 = s2[(size_t)j0 * 32 + lane];
            uint2 v1 = s2[(size_t)j1 * 32 + lane];
            uint2 v2 = s2[(size_t)j2 * 32 + lane];
            uint2 v3 = s2[(size_t)j3 * 32 + lane];
            px = __hadd2(__hadd2(*(__half2*)&v0.x, *(__half2*)&v1.x),
                         __hadd2(*(__half2*)&v2.x, *(__half2*)&v3.x));
            py = __hadd2(__hadd2(*(__half2*)&v0.y, *(__half2*)&v1.y),
                         __hadd2(*(__half2*)&v2.y, *(__half2*)&v3.y));
        }
        {
            int j0 = g_adj[e + 4], j1 = g_adj[e + 5];
            int j2 = g_adj[e + 6], j3 = g_adj[e + 7];
            uint2 v0 = s2[(size_t)j0 * 32 + lane];
            uint2 v1 = s2[(size_t)j1 * 32 + lane];
            uint2 v2 = s2[(size_t)j2 * 32 + lane];
            uint2 v3 = s2[(size_t)j3 * 32 + lane];
            px = __hadd2(px, __hadd2(__hadd2(*(__half2*)&v0.x, *(__half2*)&v1.x),
                                     __hadd2(*(__half2*)&v2.x, *(__half2*)&v3.x)));
            py = __hadd2(py, __hadd2(__hadd2(*(__half2*)&v0.y, *(__half2*)&v1.y),
                                     __hadd2(*(__half2*)&v2.y, *(__half2*)&v3.y)));
        }
        float2 fx = __half22float2(px);
        float2 fy = __half22float2(py);
        ax += fx.x; ay += fx.y; az += fy.x; aw += fy.y;
    }
    for (; e + 4 <= end; e += 4) {
        int j0 = g_adj[e],     j1 = g_adj[e + 1];
        int j2 = g_adj[e + 2], j3 = g_adj[e + 3];
        uint2 v0 = s2[(size_t)j0 * 32 + lane];
        uint2 v1 = s2[(size_t)j1 * 32 + lane];
        uint2 v2 = s2[(size_t)j2 * 32 + lane];
        uint2 v3 = s2[(size_t)j3 * 32 + lane];
        __half2 sx = __hadd2(__hadd2(*(__half2*)&v0.x, *(__half2*)&v1.x),
                             __hadd2(*(__half2*)&v2.x, *(__half2*)&v3.x));
        __half2 sy = __hadd2(__hadd2(*(__half2*)&v0.y, *(__half2*)&v1.y),
                             __hadd2(*(__half2*)&v2.y, *(__half2*)&v3.y));
        float2 fx = __half22float2(sx);
        float2 fy = __half22float2(sy);
        ax += fx.x; ay += fx.y; az += fy.x; aw += fy.y;
    }
    for (; e < end; e++) {
        int j = g_adj[e];
        uint2 u = s2[(size_t)j * 32 + lane];
        float2 f0 = __half22float2(*(__half2*)&u.x);
        float2 f1 = __half22float2(*(__half2*)&u.y);
        ax += f0.x; ay += f0.y; az += f1.x; aw += f1.y;
    }

    float inv = g_invdeg[warp];
    ax *= inv; ay *= inv; az *= inv; aw *= inv;
    if (BR) {
        float4 bv = *(const float4*)&bias[lane * 4];
        ax = fmaxf(ax + bv.x, 0.f);
        ay = fmaxf(ay + bv.y, 0.f);
        az = fmaxf(az + bv.z, 0.f);
        aw = fmaxf(aw + bv.w, 0.f);
    }
    if (HOUT) {
        __half2 h0 = __floats2half2_rn(ax, ay);
        __half2 h1 = __floats2half2_rn(az, aw);
        uint2 u;
        u.x = *(unsigned*)&h0; u.y = *(unsigned*)&h1;
        ((uint2*)dstv)[rowbase + lane] = u;
    } else {
        ((float4*)dstv)[(size_t)warp * 32 + lane] = make_float4(ax, ay, az, aw);
    }
}

// ---------------- HMMA GEMM (proven R11): tile 128x128, 8 warps, m16n8k16 ----------------
#define SPITCH 136
template <bool F16SRC, bool POST>
__global__ void __launch_bounds__(256, 2)
gemm_mma_kernel(const void* __restrict__ Asrc, const __half* __restrict__ Wt,
                const float* __restrict__ bias,
                const __half* __restrict__ Wct, const float* __restrict__ bc,
                void* __restrict__ dstv, int M) {
    extern __shared__ __half smh[];
    __half* Ws  = smh;
    __half* As  = smh + 128 * SPITCH;
    __half* Wcs = smh + 2 * 128 * SPITCH;

    int tid  = threadIdx.x;
    int wid  = tid >> 5;
    int lane = tid & 31;
    int g    = lane >> 2;
    int tig  = lane & 3;
    int m0   = blockIdx.x * 128;

    for (int j = 0; j < 8; j++) {
        int i = tid + j * 256;
        int r = i >> 4, c8 = i & 15;
        *(uint4*)&Ws[r * SPITCH + c8 * 8] = *(const uint4*)&Wt[r * KDIM + c8 * 8];
    }
    if (POST) {
        for (int j = 0; j < 4; j++) {
            int i = tid + j * 256;
            int r = i >> 4, c8 = i & 15;
            *(uint4*)&Wcs[r * SPITCH + c8 * 8] = *(const uint4*)&Wct[r * KDIM + c8 * 8];
        }
    }

    if (F16SRC) {
        const __half* Ah = (const __half*)Asrc;
        for (int j = 0; j < 8; j++) {
            int i = tid + j * 256;
            int r = i >> 4, c8 = i & 15;
            int gr = m0 + r;
            uint4 v = make_uint4(0, 0, 0, 0);
            if (gr < M) v = *(const uint4*)&Ah[(size_t)gr * KDIM + c8 * 8];
            *(uint4*)&As[r * SPITCH + c8 * 8] = v;
        }
    } else {
        const float4* Af = (const float4*)Asrc;
        for (int j = 0; j < 16; j++) {
            int i = tid + j * 256;
            int r = i >> 5, c4 = i & 31;
            int gr = m0 + r;
            float4 v = make_float4(0.f, 0.f, 0.f, 0.f);
            if (gr < M) v = Af[(size_t)gr * 32 + c4];
            __half2 h0 = __floats2half2_rn(v.x, v.y);
            __half2 h1 = __floats2half2_rn(v.z, v.w);
            uint2 u; u.x = *(u32*)&h0; u.y = *(u32*)&h1;
            *(uint2*)&As[r * SPITCH + c4 * 4] = u;
        }
    }
    __syncthreads();

    int rowW = (wid & 3) * 32;
    int colW = (wid >> 2) * 64;

    float c[2][8][4];
#pragma unroll
    for (int mt = 0; mt < 2; mt++)
#pragma unroll
        for (int nt = 0; nt < 8; nt++)
#pragma unroll
            for (int p = 0; p < 4; p++) c[mt][nt][p] = 0.f;

#pragma unroll
    for (int ks = 0; ks < 8; ks++) {
        int kb = ks * 16;
        u32 a[2][4];
#pragma unroll
        for (int mt = 0; mt < 2; mt++) {
            int r0 = rowW + mt * 16 + g;
            a[mt][0] = *(const u32*)&As[r0 * SPITCH + kb + tig * 2];
            a[mt][1] = *(const u32*)&As[(r0 + 8) * SPITCH + kb + tig * 2];
            a[mt][2] = *(const u32*)&As[r0 * SPITCH + kb + 8 + tig * 2];
            a[mt][3] = *(const u32*)&As[(r0 + 8) * SPITCH + kb + 8 + tig * 2];
        }
#pragma unroll
        for (int nt = 0; nt < 8; nt++) {
            int n = colW + nt * 8 + g;
            u32 b[2];
            b[0] = *(const u32*)&Ws[n * SPITCH + kb + tig * 2];
            b[1] = *(const u32*)&Ws[n * SPITCH + kb + 8 + tig * 2];
            mma16816(c[0][nt], a[0], b);
            mma16816(c[1][nt], a[1], b);
        }
    }

    if (!POST) {
        __half* dsth = (__half*)dstv;
#pragma unroll
        for (int mt = 0; mt < 2; mt++) {
            int r0 = m0 + rowW + mt * 16 + g;
#pragma unroll
            for (int nt = 0; nt < 8; nt++) {
                int col = colW + nt * 8 + tig * 2;
                if (r0 < M) {
                    __half2 h = __floats2half2_rn(c[mt][nt][0], c[mt][nt][1]);
                    *(u32*)&dsth[(size_t)r0 * KDIM + col] = *(u32*)&h;
                }
                if (r0 + 8 < M) {
                    __half2 h = __floats2half2_rn(c[mt][nt][2], c[mt][nt][3]);
                    *(u32*)&dsth[(size_t)(r0 + 8) * KDIM + col] = *(u32*)&h;
                }
            }
        }
        return;
    }

    __syncthreads();
#pragma unroll
    for (int mt = 0; mt < 2; mt++) {
        int lr = rowW + mt * 16 + g;
#pragma unroll
        for (int nt = 0; nt < 8; nt++) {
            int col = colW + nt * 8 + tig * 2;
            float2 bv = *(const float2*)&bias[col];
            float o0 = fmaxf(c[mt][nt][0] + bv.x, 0.f);
            float o1 = fmaxf(c[mt][nt][1] + bv.y, 0.f);
            float o2 = fmaxf(c[mt][nt][2] + bv.x, 0.f);
            float o3 = fmaxf(c[mt][nt][3] + bv.y, 0.f);
            __half2 hA = __floats2half2_rn(o0, o1);
            __half2 hB = __floats2half2_rn(o2, o3);
            *(u32*)&As[lr * SPITCH + col] = *(u32*)&hA;
            *(u32*)&As[(lr + 8) * SPITCH + col] = *(u32*)&hB;
        }
    }
    __syncthreads();

    int rowB = wid * 16;
    float d[8][4];
#pragma unroll
    for (int nt = 0; nt < 8; nt++)
#pragma unroll
        for (int p = 0; p < 4; p++) d[nt][p] = 0.f;

#pragma unroll
    for (int ks = 0; ks < 8; ks++) {
        int kb = ks * 16;
        u32 a[4];
        int r0 = rowB + g;
        a[0] = *(const u32*)&As[r0 * SPITCH + kb + tig * 2];
        a[1] = *(const u32*)&As[(r0 + 8) * SPITCH + kb + tig * 2];
        a[2] = *(const u32*)&As[r0 * SPITCH + kb + 8 + tig * 2];
        a[3] = *(const u32*)&As[(r0 + 8) * SPITCH + kb + 8 + tig * 2];
#pragma unroll
        for (int nt = 0; nt < 8; nt++) {
            int n = nt * 8 + g;
            u32 b[2];
            b[0] = *(const u32*)&Wcs[n * SPITCH + kb + tig * 2];
            b[1] = *(const u32*)&Wcs[n * SPITCH + kb + 8 + tig * 2];
            mma16816(d[nt], a, b);
        }
    }

    float* dstf = (float*)dstv;
    int r0 = m0 + rowB + g;
#pragma unroll
    for (int nt = 0; nt < 8; nt++) {
        int col = nt * 8 + tig * 2;
        float2 cv = *(const float2*)&bc[col];
        if (r0 < M) {
            float2 o = make_float2(d[nt][0] + cv.x, d[nt][1] + cv.y);
            *(float2*)&dstf[(size_t)r0 * OUTDIM + col] = o;
        }
        if (r0 + 8 < M) {
            float2 o = make_float2(d[nt][2] + cv.x, d[nt][3] + cv.y);
            *(float2*)&dstf[(size_t)(r0 + 8) * OUTDIM + col] = o;
        }
    }
}

// ---------------- host launch ----------------
extern "C" void kernel_launch(void* const* d_in, const int* in_sizes, int n_in,
                              void* d_out, int out_size) {
    const float* x  = (const float*)d_in[0];
    const int*   ei = (const int*)d_in[1];
    const float* W1 = (const float*)d_in[2];
    const float* b1 = (const float*)d_in[3];
    const float* W2 = (const float*)d_in[4];
    const float* b2 = (const float*)d_in[5];
    const float* W3 = (const float*)d_in[6];
    const float* b3 = (const float*)d_in[7];
    const float* W4 = (const float*)d_in[8];
    const float* b4 = (const float*)d_in[9];
    float* out = (float*)d_out;

    int M = in_sizes[0] / KDIM;         // 50000
    int E = in_sizes[1] / 2;            // 800000
    int NB = 444;                       // 3 resident CTAs/SM (regs<=42, 1536 thr/SM)

    __half *bufH1, *bufH2, *W1t, *W2t, *Wct;
    float *bc;
    cudaGetSymbolAddress((void**)&bufH1, g_bufH1);
    cudaGetSymbolAddress((void**)&bufH2, g_bufH2);
    cudaGetSymbolAddress((void**)&W1t, g_W1t);
    cudaGetSymbolAddress((void**)&W2t, g_W2t);
    cudaGetSymbolAddress((void**)&Wct, g_Wct);
    cudaGetSymbolAddress((void**)&bc, g_bc);

    constexpr int SMEM1 = 2 * 128 * SPITCH * 2;              // 69632 B
    constexpr int SMEM2 = (2 * 128 + 64) * SPITCH * 2;       // 87040 B
    cudaFuncSetAttribute(gemm_mma_kernel<false, false>,
                         cudaFuncAttributeMaxDynamicSharedMemorySize, SMEM1);
    cudaFuncSetAttribute(gemm_mma_kernel<true, true>,
                         cudaFuncAttributeMaxDynamicSharedMemorySize, SMEM2);

    int spmm_blocks = (M * 32 + 255) / 256;
    int gblocks = (M + 127) / 128;      // 391

    prep_w_kernel<<<256, 128>>>(W1, W2);
    prep_wc_kernel<<<OUTDIM, 128>>>(W3, b3, W4, b4);     // resets g_done
    // g1 = x @ W1 (independent of CSR)
    gemm_mma_kernel<false, false><<<gblocks, 256, SMEM1>>>(x, W1t, nullptr, nullptr,
                                                           nullptr, bufH1, M);
    csr_all_kernel<<<NB, 512>>>(ei, E, M, NB);

    // h1 = relu(A*g1 + b1)
    spmm_h_kernel<true, true><<<spmm_blocks, 256>>>(bufH1, b1, bufH2, M);
    // g2 = A*h1
    spmm_h_kernel<false, true><<<spmm_blocks, 256>>>(bufH2, nullptr, bufH1, M);
    // out = relu(g2@W2 + b2)@Wc + bc
    gemm_mma_kernel<true, true><<<gblocks, 256, SMEM2>>>(bufH1, W2t, b2, Wct, bc, out, M);
}

// round 16
// speedup vs baseline: 1.0352x; 1.0352x over previous
#include <cuda_runtime.h>
#include <cuda_fp16.h>
#include <cstdint>

#define NN      50000
#define EE      800000
#define KDIM    128
#define OUTDIM  64

typedef unsigned long long u64;
typedef unsigned int u32;

// ---------------- device scratch ----------------
__device__ __half g_bufH1[NN * KDIM];    // g1 = x@W1 ; later g2 = A*h1
__device__ __half g_bufH2[NN * KDIM];    // h1 = relu(A*g1 + b1)
__device__ __half g_W1t[KDIM * KDIM];    // W1^T fp16 [n][k]
__device__ __half g_W2t[KDIM * KDIM];    // W2^T fp16 [n][k]
__device__ __half g_Wct[OUTDIM * KDIM];  // (W3@W4)^T fp16 [n][k]
__device__ float  g_bc[OUTDIM];          // b3@W4 + b4
__device__ int    g_cnt[NN];
__device__ int    g_rowptr[NN + 1];
__device__ int    g_cursor[NN];
__device__ int    g_adj[EE];
__device__ float  g_invdeg[NN];
__device__ int    g_is64;
__device__ int    g_bsum[512];
__device__ int    g_done;

// ---------------- mma helper ----------------
__device__ __forceinline__ void mma16816(float* c, const u32* a, const u32* b) {
    asm volatile(
        "mma.sync.aligned.m16n8k16.row.col.f32.f16.f16.f32 "
        "{%0,%1,%2,%3}, {%4,%5,%6,%7}, {%8,%9}, {%0,%1,%2,%3};"
        : "+f"(c[0]), "+f"(c[1]), "+f"(c[2]), "+f"(c[3])
        : "r"(a[0]), "r"(a[1]), "r"(a[2]), "r"(a[3]), "r"(b[0]), "r"(b[1]));
}

// ---------------- prep_w: W1t/W2t fp16 transposed + zero g_cnt ----------------
__global__ void prep_w_kernel(const float* __restrict__ W1,
                              const float* __restrict__ W2, int M) {
    int b = blockIdx.x, t = threadIdx.x;   // 256 blocks x 128
    if (b < 128) {
        g_W1t[t * KDIM + b] = __float2half(W1[b * KDIM + t]);
    } else {
        int k = b - 128;
        g_W2t[t * KDIM + k] = __float2half(W2[k * KDIM + t]);
    }
    // zero counters (grid-stride over M)
    for (int i = b * 128 + t; i < M; i += 256 * 128) g_cnt[i] = 0;
}

// ---------------- prep_wc: Wct fp16 + bc; dtype detect; resets g_done ----------------
__global__ void prep_wc_kernel(const float* __restrict__ W3, const float* __restrict__ b3,
                               const float* __restrict__ W4, const float* __restrict__ b4,
                               const int* __restrict__ ei) {
    int n = blockIdx.x, t = threadIdx.x;   // 64 blocks x 128
    if (n == 0 && t == 0) {
        g_done = 0;
        int allz = 1;
        for (int e = 0; e < 64; e++) {
            if (ei[2 * e + 1] != 0) { allz = 0; break; }
        }
        g_is64 = allz;
    }
    float s = 0.0f;
    for (int m = 0; m < KDIM; m++)
        s += W3[t * KDIM + m] * W4[m * OUTDIM + n];
    g_Wct[n * KDIM + t] = __float2half(s);
    if (t == 0) {
        float sb = b4[n];
        for (int m = 0; m < KDIM; m++)
            sb += b3[m] * W4[m * OUTDIM + n];
        g_bc[n] = sb;
    }
}

// ---------------- resident-grid spin barrier with sleep backoff ----------------
__device__ __forceinline__ void gridbar(int target) {
    __syncthreads();
    if (threadIdx.x == 0) {
        __threadfence();
        atomicAdd(&g_done, 1);
        while (*(volatile int*)&g_done < target) __nanosleep(128);
    }
    __syncthreads();
}

// ---------------- persistent CSR build: count -> scan -> emit -> fill (3 barriers) ----------------
__global__ void __launch_bounds__(512, 3)
csr_all_kernel(const int* __restrict__ ei, int E, int M, int NB) {
    __shared__ int sh[512];
    int b = blockIdx.x, t = threadIdx.x;
    int gstride = NB * 512;
    int is64 = g_is64;

    // phase 1: count, 4-way batched loads (MLP=4)
    {
        int e = b * 512 + t;
        for (; e + 3 * gstride < E; e += 4 * gstride) {
            int e1 = e + gstride, e2 = e + 2 * gstride, e3 = e + 3 * gstride;
            int r0 = is64 ? ei[2 * e]  : ei[e];
            int r1 = is64 ? ei[2 * e1] : ei[e1];
            int r2 = is64 ? ei[2 * e2] : ei[e2];
            int r3 = is64 ? ei[2 * e3] : ei[e3];
            atomicAdd(&g_cnt[r0], 1);
            atomicAdd(&g_cnt[r1], 1);
            atomicAdd(&g_cnt[r2], 1);
            atomicAdd(&g_cnt[r3], 1);
        }
        for (; e < E; e += gstride) {
            int r = is64 ? ei[2 * e] : ei[e];
            atomicAdd(&g_cnt[r], 1);
        }
    }
    gridbar(NB);

    int CH = (M + NB - 1) / NB;          // 113 for NB=444
    int lo = b * CH;
    int hi = lo + CH; if (hi > M) hi = M;
    {
        int s = 0;
        for (int i = lo + t; i < hi; i += 512) s += __ldcg(&g_cnt[i]);
        sh[t] = s; __syncthreads();
        for (int d = 256; d > 0; d >>= 1) {
            if (t < d) sh[t] += sh[t + d];
            __syncthreads();
        }
        if (t == 0) g_bsum[b] = sh[0];
    }
    gridbar(2 * NB);

    // every block scans all NB (<=512) chunk sums
    int boff, total;
    {
        int v = (t < NB) ? __ldcg(&g_bsum[t]) : 0;
        sh[t] = v;
        __syncthreads();
        for (int d = 1; d < 512; d <<= 1) {
            int u = (t >= d) ? sh[t - d] : 0;
            __syncthreads();
            sh[t] += u;
            __syncthreads();
        }
        total = sh[NB - 1];
        boff  = (b > 0) ? sh[b - 1] : 0;
        __syncthreads();
    }

    // emit rowptr/cursor/invdeg for this chunk (CH <= 512, thread t = row lo+t)
    {
        int row = lo + t;
        int v = (t < CH && row < M) ? __ldcg(&g_cnt[row]) : 0;
        sh[t] = v; __syncthreads();
        for (int d = 1; d < 512; d <<= 1) {
            int u = (t >= d) ? sh[t - d] : 0;
            __syncthreads();
            sh[t] += u;
            __syncthreads();
        }
        int ex = boff + sh[t] - v;
        if (t < CH && row < M) {
            g_rowptr[row] = ex;
            g_cursor[row] = ex;
            g_invdeg[row] = 1.0f / (float)(v + 1);
        }
        if (b == 0 && t == 0) g_rowptr[M] = total;
    }
    gridbar(3 * NB);

    // phase 4: fill, 4-way batched
    {
        int e = b * 512 + t;
        for (; e + 3 * gstride < E; e += 4 * gstride) {
            int e1 = e + gstride, e2 = e + 2 * gstride, e3 = e + 3 * gstride;
            int r0, c0, r1, c1, r2, c2, r3, c3;
            if (is64) {
                r0 = ei[2 * e];  c0 = ei[2 * E + 2 * e];
                r1 = ei[2 * e1]; c1 = ei[2 * E + 2 * e1];
                r2 = ei[2 * e2]; c2 = ei[2 * E + 2 * e2];
                r3 = ei[2 * e3]; c3 = ei[2 * E + 2 * e3];
            } else {
                r0 = ei[e];  c0 = ei[E + e];
                r1 = ei[e1]; c1 = ei[E + e1];
                r2 = ei[e2]; c2 = ei[E + e2];
                r3 = ei[e3]; c3 = ei[E + e3];
            }
            int p0 = atomicAdd(&g_cursor[r0], 1);
            int p1 = atomicAdd(&g_cursor[r1], 1);
            int p2 = atomicAdd(&g_cursor[r2], 1);
            int p3 = atomicAdd(&g_cursor[r3], 1);
            g_adj[p0] = c0;
            g_adj[p1] = c1;
            g_adj[p2] = c2;
            g_adj[p3] = c3;
        }
        for (; e < E; e += gstride) {
            int r, c;
            if (is64) { r = ei[2 * e]; c = ei[2 * E + 2 * e]; }
            else      { r = ei[e];     c = ei[E + e]; }
            int p = atomicAdd(&g_cursor[r], 1);
            g_adj[p] = c;
        }
    }
}

// ---------------- SpMM: two-stage 8-edge fp16 tree, <=32 regs (proven R14) ----------------
template <bool BR, bool HOUT>
__global__ void __launch_bounds__(256, 8)
spmm_h_kernel(const __half* __restrict__ src,
              const float* __restrict__ bias,
              void* __restrict__ dstv, int M) {
    int warp = (blockIdx.x * blockDim.x + threadIdx.x) >> 5;
    if (warp >= M) return;
    int lane = threadIdx.x & 31;

    const uint2* s2 = (const uint2*)src;
    size_t rowbase = (size_t)warp * 32;

    float ax, ay, az, aw;
    {
        uint2 u = s2[rowbase + lane];
        float2 f0 = __half22float2(*(__half2*)&u.x);
        float2 f1 = __half22float2(*(__half2*)&u.y);
        ax = f0.x; ay = f0.y; az = f1.x; aw = f1.y;
    }

    int e   = g_rowptr[warp];
    int end = g_rowptr[warp + 1];

    for (; e + 8 <= end; e += 8) {
        __half2 px, py;
        {
            int j0 = g_adj[e],     j1 = g_adj[e + 1];
            int j2 = g_adj[e + 2], j3 = g_adj[e + 3];
            uint2 v0 = s2[(size_t)j0 * 32 + lane];
            uint2 v1 = s2[(size_t)j1 * 32 + lane];
            uint2 v2 = s2[(size_t)j2 * 32 + lane];
            uint2 v3 = s2[(size_t)j3 * 32 + lane];
            px = __hadd2(__hadd2(*(__half2*)&v0.x, *(__half2*)&v1.x),
                         __hadd2(*(__half2*)&v2.x, *(__half2*)&v3.x));
            py = __hadd2(__hadd2(*(__half2*)&v0.y, *(__half2*)&v1.y),
                         __hadd2(*(__half2*)&v2.y, *(__half2*)&v3.y));
        }
        {
            int j0 = g_adj[e + 4], j1 = g_adj[e + 5];
            int j2 = g_adj[e + 6], j3 = g_adj[e + 7];
            uint2 v0 = s2[(size_t)j0 * 32 + lane];
            uint2 v1 = s2[(size_t)j1 * 32 + lane];
            uint2 v2 = s2[(size_t)j2 * 32 + lane];
            uint2 v3 = s2[(size_t)j3 * 32 + lane];
            px = __hadd2(px, __hadd2(__hadd2(*(__half2*)&v0.x, *(__half2*)&v1.x),
                                     __hadd2(*(__half2*)&v2.x, *(__half2*)&v3.x)));
            py = __hadd2(py, __hadd2(__hadd2(*(__half2*)&v0.y, *(__half2*)&v1.y),
                                     __hadd2(*(__half2*)&v2.y, *(__half2*)&v3.y)));
        }
        float2 fx = __half22float2(px);
        float2 fy = __half22float2(py);
        ax += fx.x; ay += fx.y; az += fy.x; aw += fy.y;
    }
    for (; e + 4 <= end; e += 4) {
        int j0 = g_adj[e],     j1 = g_adj[e + 1];
        int j2 = g_adj[e + 2], j3 = g_adj[e + 3];
        uint2 v0 = s2[(size_t)j0 * 32 + lane];
        uint2 v1 = s2[(size_t)j1 * 32 + lane];
        uint2 v2 = s2[(size_t)j2 * 32 + lane];
        uint2 v3 = s2[(size_t)j3 * 32 + lane];
        __half2 sx = __hadd2(__hadd2(*(__half2*)&v0.x, *(__half2*)&v1.x),
                             __hadd2(*(__half2*)&v2.x, *(__half2*)&v3.x));
        __half2 sy = __hadd2(__hadd2(*(__half2*)&v0.y, *(__half2*)&v1.y),
                             __hadd2(*(__half2*)&v2.y, *(__half2*)&v3.y));
        float2 fx = __half22float2(sx);
        float2 fy = __half22float2(sy);
        ax += fx.x; ay += fx.y; az += fy.x; aw += fy.y;
    }
    for (; e < end; e++) {
        int j = g_adj[e];
        uint2 u = s2[(size_t)j * 32 + lane];
        float2 f0 = __half22float2(*(__half2*)&u.x);
        float2 f1 = __half22float2(*(__half2*)&u.y);
        ax += f0.x; ay += f0.y; az += f1.x; aw += f1.y;
    }

    float inv = g_invdeg[warp];
    ax *= inv; ay *= inv; az *= inv; aw *= inv;
    if (BR) {
        float4 bv = *(const float4*)&bias[lane * 4];
        ax = fmaxf(ax + bv.x, 0.f);
        ay = fmaxf(ay + bv.y, 0.f);
        az = fmaxf(az + bv.z, 0.f);
        aw = fmaxf(aw + bv.w, 0.f);
    }
    if (HOUT) {
        __half2 h0 = __floats2half2_rn(ax, ay);
        __half2 h1 = __floats2half2_rn(az, aw);
        uint2 u;
        u.x = *(unsigned*)&h0; u.y = *(unsigned*)&h1;
        ((uint2*)dstv)[rowbase + lane] = u;
    } else {
        ((float4*)dstv)[(size_t)warp * 32 + lane] = make_float4(ax, ay, az, aw);
    }
}

// ---------------- HMMA GEMM (proven R11): tile 128x128, 8 warps, m16n8k16 ----------------
#define SPITCH 136
template <bool F16SRC, bool POST>
__global__ void __launch_bounds__(256, 2)
gemm_mma_kernel(const void* __restrict__ Asrc, const __half* __restrict__ Wt,
                const float* __restrict__ bias,
                const __half* __restrict__ Wct, const float* __restrict__ bc,
                void* __restrict__ dstv, int M) {
    extern __shared__ __half smh[];
    __half* Ws  = smh;
    __half* As  = smh + 128 * SPITCH;
    __half* Wcs = smh + 2 * 128 * SPITCH;

    int tid  = threadIdx.x;
    int wid  = tid >> 5;
    int lane = tid & 31;
    int g    = lane >> 2;
    int tig  = lane & 3;
    int m0   = blockIdx.x * 128;

    for (int j = 0; j < 8; j++) {
        int i = tid + j * 256;
        int r = i >> 4, c8 = i & 15;
        *(uint4*)&Ws[r * SPITCH + c8 * 8] = *(const uint4*)&Wt[r * KDIM + c8 * 8];
    }
    if (POST) {
        for (int j = 0; j < 4; j++) {
            int i = tid + j * 256;
            int r = i >> 4, c8 = i & 15;
            *(uint4*)&Wcs[r * SPITCH + c8 * 8] = *(const uint4*)&Wct[r * KDIM + c8 * 8];
        }
    }

    if (F16SRC) {
        const __half* Ah = (const __half*)Asrc;
        for (int j = 0; j < 8; j++) {
            int i = tid + j * 256;
            int r = i >> 4, c8 = i & 15;
            int gr = m0 + r;
            uint4 v = make_uint4(0, 0, 0, 0);
            if (gr < M) v = *(const uint4*)&Ah[(size_t)gr * KDIM + c8 * 8];
            *(uint4*)&As[r * SPITCH + c8 * 8] = v;
        }
    } else {
        const float4* Af = (const float4*)Asrc;
        for (int j = 0; j < 16; j++) {
            int i = tid + j * 256;
            int r = i >> 5, c4 = i & 31;
            int gr = m0 + r;
            float4 v = make_float4(0.f, 0.f, 0.f, 0.f);
            if (gr < M) v = Af[(size_t)gr * 32 + c4];
            __half2 h0 = __floats2half2_rn(v.x, v.y);
            __half2 h1 = __floats2half2_rn(v.z, v.w);
            uint2 u; u.x = *(u32*)&h0; u.y = *(u32*)&h1;
            *(uint2*)&As[r * SPITCH + c4 * 4] = u;
        }
    }
    __syncthreads();

    int rowW = (wid & 3) * 32;
    int colW = (wid >> 2) * 64;

    float c[2][8][4];
#pragma unroll
    for (int mt = 0; mt < 2; mt++)
#pragma unroll
        for (int nt = 0; nt < 8; nt++)
#pragma unroll
            for (int p = 0; p < 4; p++) c[mt][nt][p] = 0.f;

#pragma unroll
    for (int ks = 0; ks < 8; ks++) {
        int kb = ks * 16;
        u32 a[2][4];
#pragma unroll
        for (int mt = 0; mt < 2; mt++) {
            int r0 = rowW + mt * 16 + g;
            a[mt][0] = *(const u32*)&As[r0 * SPITCH + kb + tig * 2];
            a[mt][1] = *(const u32*)&As[(r0 + 8) * SPITCH + kb + tig * 2];
            a[mt][2] = *(const u32*)&As[r0 * SPITCH + kb + 8 + tig * 2];
            a[mt][3] = *(const u32*)&As[(r0 + 8) * SPITCH + kb + 8 + tig * 2];
        }
#pragma unroll
        for (int nt = 0; nt < 8; nt++) {
            int n = colW + nt * 8 + g;
            u32 b[2];
            b[0] = *(const u32*)&Ws[n * SPITCH + kb + tig * 2];
            b[1] = *(const u32*)&Ws[n * SPITCH + kb + 8 + tig * 2];
            mma16816(c[0][nt], a[0], b);
            mma16816(c[1][nt], a[1], b);
        }
    }

    if (!POST) {
        __half* dsth = (__half*)dstv;
#pragma unroll
        for (int mt = 0; mt < 2; mt++) {
            int r0 = m0 + rowW + mt * 16 + g;
#pragma unroll
            for (int nt = 0; nt < 8; nt++) {
                int col = colW + nt * 8 + tig * 2;
                if (r0 < M) {
                    __half2 h = __floats2half2_rn(c[mt][nt][0], c[mt][nt][1]);
                    *(u32*)&dsth[(size_t)r0 * KDIM + col] = *(u32*)&h;
                }
                if (r0 + 8 < M) {
                    __half2 h = __floats2half2_rn(c[mt][nt][2], c[mt][nt][3]);
                    *(u32*)&dsth[(size_t)(r0 + 8) * KDIM + col] = *(u32*)&h;
                }
            }
        }
        return;
    }

    __syncthreads();
#pragma unroll
    for (int mt = 0; mt < 2; mt++) {
        int lr = rowW + mt * 16 + g;
#pragma unroll
        for (int nt = 0; nt < 8; nt++) {
            int col = colW + nt * 8 + tig * 2;
            float2 bv = *(const float2*)&bias[col];
            float o0 = fmaxf(c[mt][nt][0] + bv.x, 0.f);
            float o1 = fmaxf(c[mt][nt][1] + bv.y, 0.f);
            float o2 = fmaxf(c[mt][nt][2] + bv.x, 0.f);
            float o3 = fmaxf(c[mt][nt][3] + bv.y, 0.f);
            __half2 hA = __floats2half2_rn(o0, o1);
            __half2 hB = __floats2half2_rn(o2, o3);
            *(u32*)&As[lr * SPITCH + col] = *(u32*)&hA;
            *(u32*)&As[(lr + 8) * SPITCH + col] = *(u32*)&hB;
        }
    }
    __syncthreads();

    int rowB = wid * 16;
    float d[8][4];
#pragma unroll
    for (int nt = 0; nt < 8; nt++)
#pragma unroll
        for (int p = 0; p < 4; p++) d[nt][p] = 0.f;

#pragma unroll
    for (int ks = 0; ks < 8; ks++) {
        int kb = ks * 16;
        u32 a[4];
        int r0 = rowB + g;
        a[0] = *(const u32*)&As[r0 * SPITCH + kb + tig * 2];
        a[1] = *(const u32*)&As[(r0 + 8) * SPITCH + kb + tig * 2];
        a[2] = *(const u32*)&As[r0 * SPITCH + kb + 8 + tig * 2];
        a[3] = *(const u32*)&As[(r0 + 8) * SPITCH + kb + 8 + tig * 2];
#pragma unroll
        for (int nt = 0; nt < 8; nt++) {
            int n = nt * 8 + g;
            u32 b[2];
            b[0] = *(const u32*)&Wcs[n * SPITCH + kb + tig * 2];
            b[1] = *(const u32*)&Wcs[n * SPITCH + kb + 8 + tig * 2];
            mma16816(d[nt], a, b);
        }
    }

    float* dstf = (float*)dstv;
    int r0 = m0 + rowB + g;
#pragma unroll
    for (int nt = 0; nt < 8; nt++) {
        int col = nt * 8 + tig * 2;
        float2 cv = *(const float2*)&bc[col];
        if (r0 < M) {
            float2 o = make_float2(d[nt][0] + cv.x, d[nt][1] + cv.y);
            *(float2*)&dstf[(size_t)r0 * OUTDIM + col] = o;
        }
        if (r0 + 8 < M) {
            float2 o = make_float2(d[nt][2] + cv.x, d[nt][3] + cv.y);
            *(float2*)&dstf[(size_t)(r0 + 8) * OUTDIM + col] = o;
        }
    }
}

// ---------------- host launch ----------------
extern "C" void kernel_launch(void* const* d_in, const int* in_sizes, int n_in,
                              void* d_out, int out_size) {
    const float* x  = (const float*)d_in[0];
    const int*   ei = (const int*)d_in[1];
    const float* W1 = (const float*)d_in[2];
    const float* b1 = (const float*)d_in[3];
    const float* W2 = (const float*)d_in[4];
    const float* b2 = (const float*)d_in[5];
    const float* W3 = (const float*)d_in[6];
    const float* b3 = (const float*)d_in[7];
    const float* W4 = (const float*)d_in[8];
    const float* b4 = (const float*)d_in[9];
    float* out = (float*)d_out;

    int M = in_sizes[0] / KDIM;         // 50000
    int E = in_sizes[1] / 2;            // 800000
    int NB = 444;                       // 3 resident CTAs/SM

    __half *bufH1, *bufH2, *W1t, *W2t, *Wct;
    float *bc;
    cudaGetSymbolAddress((void**)&bufH1, g_bufH1);
    cudaGetSymbolAddress((void**)&bufH2, g_bufH2);
    cudaGetSymbolAddress((void**)&W1t, g_W1t);
    cudaGetSymbolAddress((void**)&W2t, g_W2t);
    cudaGetSymbolAddress((void**)&Wct, g_Wct);
    cudaGetSymbolAddress((void**)&bc, g_bc);

    constexpr int SMEM1 = 2 * 128 * SPITCH * 2;              // 69632 B
    constexpr int SMEM2 = (2 * 128 + 64) * SPITCH * 2;       // 87040 B
    cudaFuncSetAttribute(gemm_mma_kernel<false, false>,
                         cudaFuncAttributeMaxDynamicSharedMemorySize, SMEM1);
    cudaFuncSetAttribute(gemm_mma_kernel<true, true>,
                         cudaFuncAttributeMaxDynamicSharedMemorySize, SMEM2);

    int spmm_blocks = (M * 32 + 255) / 256;
    int gblocks = (M + 127) / 128;      // 391

    prep_w_kernel<<<256, 128>>>(W1, W2, M);                  // + zero g_cnt
    prep_wc_kernel<<<OUTDIM, 128>>>(W3, b3, W4, b4, ei);     // + detect, reset g_done
    // g1 = x @ W1 (independent of CSR)
    gemm_mma_kernel<false, false><<<gblocks, 256, SMEM1>>>(x, W1t, nullptr, nullptr,
                                                           nullptr, bufH1, M);
    csr_all_kernel<<<NB, 512>>>(ei, E, M, NB);

    // h1 = relu(A*g1 + b1)
    spmm_h_kernel<true, true><<<spmm_blocks, 256>>>(bufH1, b1, bufH2, M);
    // g2 = A*h1
    spmm_h_kernel<false, true><<<spmm_blocks, 256>>>(bufH2, nullptr, bufH1, M);
    // out = relu(g2@W2 + b2)@Wc + bc
    gemm_mma_kernel<true, true><<<gblocks, 256, SMEM2>>>(bufH1, W2t, b2, Wct, bc, out, M);
}

// round 17
// speedup vs baseline: 1.0927x; 1.0555x over previous
#include <cuda_runtime.h>
#include <cuda_fp16.h>
#include <cstdint>

#define NN      50000
#define EE      800000
#define KDIM    128
#define OUTDIM  64

typedef unsigned long long u64;
typedef unsigned int u32;

// ---------------- device scratch ----------------
__device__ __half g_bufH1[NN * KDIM];    // g1 = x@W1 ; later g2 = A*h1
__device__ __half g_bufH2[NN * KDIM];    // h1 = relu(A*g1 + b1)
__device__ __half g_W1t[KDIM * KDIM];
__device__ __half g_W2t[KDIM * KDIM];
__device__ __half g_Wct[OUTDIM * KDIM];
__device__ float  g_bc[OUTDIM];
__device__ int    g_cnt[NN];
__device__ int    g_rowptr[NN + 1];
__device__ int    g_adj[EE];
__device__ int    g_pos[EE];             // per-edge slot within its row
__device__ float  g_invdeg[NN];
__device__ int    g_is64;
__device__ int    g_bsum[512];
__device__ int    g_done;

// ---------------- mma helper ----------------
__device__ __forceinline__ void mma16816(float* c, const u32* a, const u32* b) {
    asm volatile(
        "mma.sync.aligned.m16n8k16.row.col.f32.f16.f16.f32 "
        "{%0,%1,%2,%3}, {%4,%5,%6,%7}, {%8,%9}, {%0,%1,%2,%3};"
        : "+f"(c[0]), "+f"(c[1]), "+f"(c[2]), "+f"(c[3])
        : "r"(a[0]), "r"(a[1]), "r"(a[2]), "r"(a[3]), "r"(b[0]), "r"(b[1]));
}

// ---------------- prep_w: W1t/W2t fp16 transposed + zero g_cnt ----------------
__global__ void prep_w_kernel(const float* __restrict__ W1,
                              const float* __restrict__ W2, int M) {
    int b = blockIdx.x, t = threadIdx.x;   // 256 blocks x 128
    if (b < 128) {
        g_W1t[t * KDIM + b] = __float2half(W1[b * KDIM + t]);
    } else {
        int k = b - 128;
        g_W2t[t * KDIM + k] = __float2half(W2[k * KDIM + t]);
    }
    for (int i = b * 128 + t; i < M; i += 256 * 128) g_cnt[i] = 0;
}

// ---------------- prep_wc: Wct fp16 + bc; dtype detect; resets g_done ----------------
__global__ void prep_wc_kernel(const float* __restrict__ W3, const float* __restrict__ b3,
                               const float* __restrict__ W4, const float* __restrict__ b4,
                               const int* __restrict__ ei) {
    int n = blockIdx.x, t = threadIdx.x;   // 64 blocks x 128
    if (n == 0 && t == 0) {
        g_done = 0;
        int allz = 1;
        for (int e = 0; e < 64; e++) {
            if (ei[2 * e + 1] != 0) { allz = 0; break; }
        }
        g_is64 = allz;
    }
    float s = 0.0f;
    for (int m = 0; m < KDIM; m++)
        s += W3[t * KDIM + m] * W4[m * OUTDIM + n];
    g_Wct[n * KDIM + t] = __float2half(s);
    if (t == 0) {
        float sb = b4[n];
        for (int m = 0; m < KDIM; m++)
            sb += b3[m] * W4[m * OUTDIM + n];
        g_bc[n] = sb;
    }
}

// ---------------- resident-grid spin barrier with sleep backoff ----------------
__device__ __forceinline__ void gridbar(int target) {
    __syncthreads();
    if (threadIdx.x == 0) {
        __threadfence();
        atomicAdd(&g_done, 1);
        while (*(volatile int*)&g_done < target) __nanosleep(128);
    }
    __syncthreads();
}

// ---------------- persistent CSR build: count(+pos) -> scan -> emit -> fill(no atomics) ----------------
__global__ void __launch_bounds__(512, 1)
csr_all_kernel(const int* __restrict__ ei, int E, int M, int NB) {
    __shared__ int sh[512];
    int b = blockIdx.x, t = threadIdx.x;
    int gstride = NB * 512;
    int is64 = g_is64;

    // phase 1: count + save slot position (atomic returns pos)
    {
        int e = b * 512 + t;
        for (; e + 3 * gstride < E; e += 4 * gstride) {
            int e1 = e + gstride, e2 = e + 2 * gstride, e3 = e + 3 * gstride;
            int r0 = is64 ? ei[2 * e]  : ei[e];
            int r1 = is64 ? ei[2 * e1] : ei[e1];
            int r2 = is64 ? ei[2 * e2] : ei[e2];
            int r3 = is64 ? ei[2 * e3] : ei[e3];
            int p0 = atomicAdd(&g_cnt[r0], 1);
            int p1 = atomicAdd(&g_cnt[r1], 1);
            int p2 = atomicAdd(&g_cnt[r2], 1);
            int p3 = atomicAdd(&g_cnt[r3], 1);
            g_pos[e]  = p0;
            g_pos[e1] = p1;
            g_pos[e2] = p2;
            g_pos[e3] = p3;
        }
        for (; e < E; e += gstride) {
            int r = is64 ? ei[2 * e] : ei[e];
            g_pos[e] = atomicAdd(&g_cnt[r], 1);
        }
    }
    gridbar(NB);

    int CH = (M + NB - 1) / NB;
    int lo = b * CH;
    int hi = lo + CH; if (hi > M) hi = M;
    {
        int s = 0;
        for (int i = lo + t; i < hi; i += 512) s += __ldcg(&g_cnt[i]);
        sh[t] = s; __syncthreads();
        for (int d = 256; d > 0; d >>= 1) {
            if (t < d) sh[t] += sh[t + d];
            __syncthreads();
        }
        if (t == 0) g_bsum[b] = sh[0];
    }
    gridbar(2 * NB);

    int boff, total;
    {
        int v = (t < NB) ? __ldcg(&g_bsum[t]) : 0;
        sh[t] = v;
        __syncthreads();
        for (int d = 1; d < 512; d <<= 1) {
            int u = (t >= d) ? sh[t - d] : 0;
            __syncthreads();
            sh[t] += u;
            __syncthreads();
        }
        total = sh[NB - 1];
        boff  = (b > 0) ? sh[b - 1] : 0;
        __syncthreads();
    }

    // emit rowptr/invdeg for this chunk (CH <= 512, thread t = row lo+t)
    {
        int row = lo + t;
        int v = (t < CH && row < M) ? __ldcg(&g_cnt[row]) : 0;
        sh[t] = v; __syncthreads();
        for (int d = 1; d < 512; d <<= 1) {
            int u = (t >= d) ? sh[t - d] : 0;
            __syncthreads();
            sh[t] += u;
            __syncthreads();
        }
        int ex = boff + sh[t] - v;
        if (t < CH && row < M) {
            g_rowptr[row] = ex;
            g_invdeg[row] = 1.0f / (float)(v + 1);
        }
        if (b == 0 && t == 0) g_rowptr[M] = total;
    }
    gridbar(3 * NB);

    // phase 4: fill, atomic-free: adj[rowptr[r] + pos[e]] = c
    {
        int e = b * 512 + t;
        for (; e + 3 * gstride < E; e += 4 * gstride) {
            int e1 = e + gstride, e2 = e + 2 * gstride, e3 = e + 3 * gstride;
            int r0, c0, r1, c1, r2, c2, r3, c3;
            if (is64) {
                r0 = ei[2 * e];  c0 = ei[2 * E + 2 * e];
                r1 = ei[2 * e1]; c1 = ei[2 * E + 2 * e1];
                r2 = ei[2 * e2]; c2 = ei[2 * E + 2 * e2];
                r3 = ei[2 * e3]; c3 = ei[2 * E + 2 * e3];
            } else {
                r0 = ei[e];  c0 = ei[E + e];
                r1 = ei[e1]; c1 = ei[E + e1];
                r2 = ei[e2]; c2 = ei[E + e2];
                r3 = ei[e3]; c3 = ei[E + e3];
            }
            int p0 = __ldcg(&g_rowptr[r0]) + g_pos[e];
            int p1 = __ldcg(&g_rowptr[r1]) + g_pos[e1];
            int p2 = __ldcg(&g_rowptr[r2]) + g_pos[e2];
            int p3 = __ldcg(&g_rowptr[r3]) + g_pos[e3];
            g_adj[p0] = c0;
            g_adj[p1] = c1;
            g_adj[p2] = c2;
            g_adj[p3] = c3;
        }
        for (; e < E; e += gstride) {
            int r, c;
            if (is64) { r = ei[2 * e]; c = ei[2 * E + 2 * e]; }
            else      { r = ei[e];     c = ei[E + e]; }
            int p = __ldcg(&g_rowptr[r]) + g_pos[e];
            g_adj[p] = c;
        }
    }
}

// ---------------- SpMM: two-stage 8-edge fp16 tree, <=32 regs (proven) ----------------
template <bool BR, bool HOUT>
__global__ void __launch_bounds__(256, 8)
spmm_h_kernel(const __half* __restrict__ src,
              const float* __restrict__ bias,
              void* __restrict__ dstv, int M) {
    int warp = (blockIdx.x * blockDim.x + threadIdx.x) >> 5;
    if (warp >= M) return;
    int lane = threadIdx.x & 31;

    const uint2* s2 = (const uint2*)src;
    size_t rowbase = (size_t)warp * 32;

    float ax, ay, az, aw;
    {
        uint2 u = s2[rowbase + lane];
        float2 f0 = __half22float2(*(__half2*)&u.x);
        float2 f1 = __half22float2(*(__half2*)&u.y);
        ax = f0.x; ay = f0.y; az = f1.x; aw = f1.y;
    }

    int e   = g_rowptr[warp];
    int end = g_rowptr[warp + 1];

    for (; e + 8 <= end; e += 8) {
        __half2 px, py;
        {
            int j0 = g_adj[e],     j1 = g_adj[e + 1];
            int j2 = g_adj[e + 2], j3 = g_adj[e + 3];
            uint2 v0 = s2[(size_t)j0 * 32 + lane];
            uint2 v1 = s2[(size_t)j1 * 32 + lane];
            uint2 v2 = s2[(size_t)j2 * 32 + lane];
            uint2 v3 = s2[(size_t)j3 * 32 + lane];
            px = __hadd2(__hadd2(*(__half2*)&v0.x, *(__half2*)&v1.x),
                         __hadd2(*(__half2*)&v2.x, *(__half2*)&v3.x));
            py = __hadd2(__hadd2(*(__half2*)&v0.y, *(__half2*)&v1.y),
                         __hadd2(*(__half2*)&v2.y, *(__half2*)&v3.y));
        }
        {
            int j0 = g_adj[e + 4], j1 = g_adj[e + 5];
            int j2 = g_adj[e + 6], j3 = g_adj[e + 7];
            uint2 v0 = s2[(size_t)j0 * 32 + lane];
            uint2 v1 = s2[(size_t)j1 * 32 + lane];
            uint2 v2 = s2[(size_t)j2 * 32 + lane];
            uint2 v3 = s2[(size_t)j3 * 32 + lane];
            px = __hadd2(px, __hadd2(__hadd2(*(__half2*)&v0.x, *(__half2*)&v1.x),
                                     __hadd2(*(__half2*)&v2.x, *(__half2*)&v3.x)));
            py = __hadd2(py, __hadd2(__hadd2(*(__half2*)&v0.y, *(__half2*)&v1.y),
                                     __hadd2(*(__half2*)&v2.y, *(__half2*)&v3.y)));
        }
        float2 fx = __half22float2(px);
        float2 fy = __half22float2(py);
        ax += fx.x; ay += fx.y; az += fy.x; aw += fy.y;
    }
    for (; e + 4 <= end; e += 4) {
        int j0 = g_adj[e],     j1 = g_adj[e + 1];
        int j2 = g_adj[e + 2], j3 = g_adj[e + 3];
        uint2 v0 = s2[(size_t)j0 * 32 + lane];
        uint2 v1 = s2[(size_t)j1 * 32 + lane];
        uint2 v2 = s2[(size_t)j2 * 32 + lane];
        uint2 v3 = s2[(size_t)j3 * 32 + lane];
        __half2 sx = __hadd2(__hadd2(*(__half2*)&v0.x, *(__half2*)&v1.x),
                             __hadd2(*(__half2*)&v2.x, *(__half2*)&v3.x));
        __half2 sy = __hadd2(__hadd2(*(__half2*)&v0.y, *(__half2*)&v1.y),
                             __hadd2(*(__half2*)&v2.y, *(__half2*)&v3.y));
        float2 fx = __half22float2(sx);
        float2 fy = __half22float2(sy);
        ax += fx.x; ay += fx.y; az += fy.x; aw += fy.y;
    }
    for (; e < end; e++) {
        int j = g_adj[e];
        uint2 u = s2[(size_t)j * 32 + lane];
        float2 f0 = __half22float2(*(__half2*)&u.x);
        float2 f1 = __half22float2(*(__half2*)&u.y);
        ax += f0.x; ay += f0.y; az += f1.x; aw += f1.y;
    }

    float inv = g_invdeg[warp];
    ax *= inv; ay *= inv; az *= inv; aw *= inv;
    if (BR) {
        float4 bv = *(const float4*)&bias[lane * 4];
        ax = fmaxf(ax + bv.x, 0.f);
        ay = fmaxf(ay + bv.y, 0.f);
        az = fmaxf(az + bv.z, 0.f);
        aw = fmaxf(aw + bv.w, 0.f);
    }
    if (HOUT) {
        __half2 h0 = __floats2half2_rn(ax, ay);
        __half2 h1 = __floats2half2_rn(az, aw);
        uint2 u;
        u.x = *(unsigned*)&h0; u.y = *(unsigned*)&h1;
        ((uint2*)dstv)[rowbase + lane] = u;
    } else {
        ((float4*)dstv)[(size_t)warp * 32 + lane] = make_float4(ax, ay, az, aw);
    }
}

// ---------------- HMMA GEMM (proven R11): tile 128x128, 8 warps, m16n8k16 ----------------
#define SPITCH 136
template <bool F16SRC, bool POST>
__global__ void __launch_bounds__(256, 2)
gemm_mma_kernel(const void* __restrict__ Asrc, const __half* __restrict__ Wt,
                const float* __restrict__ bias,
                const __half* __restrict__ Wct, const float* __restrict__ bc,
                void* __restrict__ dstv, int M) {
    extern __shared__ __half smh[];
    __half* Ws  = smh;
    __half* As  = smh + 128 * SPITCH;
    __half* Wcs = smh + 2 * 128 * SPITCH;

    int tid  = threadIdx.x;
    int wid  = tid >> 5;
    int lane = tid & 31;
    int g    = lane >> 2;
    int tig  = lane & 3;
    int m0   = blockIdx.x * 128;

    for (int j = 0; j < 8; j++) {
        int i = tid + j * 256;
        int r = i >> 4, c8 = i & 15;
        *(uint4*)&Ws[r * SPITCH + c8 * 8] = *(const uint4*)&Wt[r * KDIM + c8 * 8];
    }
    if (POST) {
        for (int j = 0; j < 4; j++) {
            int i = tid + j * 256;
            int r = i >> 4, c8 = i & 15;
            *(uint4*)&Wcs[r * SPITCH + c8 * 8] = *(const uint4*)&Wct[r * KDIM + c8 * 8];
        }
    }

    if (F16SRC) {
        const __half* Ah = (const __half*)Asrc;
        for (int j = 0; j < 8; j++) {
            int i = tid + j * 256;
            int r = i >> 4, c8 = i & 15;
            int gr = m0 + r;
            uint4 v = make_uint4(0, 0, 0, 0);
            if (gr < M) v = *(const uint4*)&Ah[(size_t)gr * KDIM + c8 * 8];
            *(uint4*)&As[r * SPITCH + c8 * 8] = v;
        }
    } else {
        const float4* Af = (const float4*)Asrc;
        for (int j = 0; j < 16; j++) {
            int i = tid + j * 256;
            int r = i >> 5, c4 = i & 31;
            int gr = m0 + r;
            float4 v = make_float4(0.f, 0.f, 0.f, 0.f);
            if (gr < M) v = Af[(size_t)gr * 32 + c4];
            __half2 h0 = __floats2half2_rn(v.x, v.y);
            __half2 h1 = __floats2half2_rn(v.z, v.w);
            uint2 u; u.x = *(u32*)&h0; u.y = *(u32*)&h1;
            *(uint2*)&As[r * SPITCH + c4 * 4] = u;
        }
    }
    __syncthreads();

    int rowW = (wid & 3) * 32;
    int colW = (wid >> 2) * 64;

    float c[2][8][4];
#pragma unroll
    for (int mt = 0; mt < 2; mt++)
#pragma unroll
        for (int nt = 0; nt < 8; nt++)
#pragma unroll
            for (int p = 0; p < 4; p++) c[mt][nt][p] = 0.f;

#pragma unroll
    for (int ks = 0; ks < 8; ks++) {
        int kb = ks * 16;
        u32 a[2][4];
#pragma unroll
        for (int mt = 0; mt < 2; mt++) {
            int r0 = rowW + mt * 16 + g;
            a[mt][0] = *(const u32*)&As[r0 * SPITCH + kb + tig * 2];
            a[mt][1] = *(const u32*)&As[(r0 + 8) * SPITCH + kb + tig * 2];
            a[mt][2] = *(const u32*)&As[r0 * SPITCH + kb + 8 + tig * 2];
            a[mt][3] = *(const u32*)&As[(r0 + 8) * SPITCH + kb + 8 + tig * 2];
        }
#pragma unroll
        for (int nt = 0; nt < 8; nt++) {
            int n = colW + nt * 8 + g;
            u32 b[2];
            b[0] = *(const u32*)&Ws[n * SPITCH + kb + tig * 2];
            b[1] = *(const u32*)&Ws[n * SPITCH + kb + 8 + tig * 2];
            mma16816(c[0][nt], a[0], b);
            mma16816(c[1][nt], a[1], b);
        }
    }

    if (!POST) {
        __half* dsth = (__half*)dstv;
#pragma unroll
        for (int mt = 0; mt < 2; mt++) {
            int r0 = m0 + rowW + mt * 16 + g;
#pragma unroll
            for (int nt = 0; nt < 8; nt++) {
                int col = colW + nt * 8 + tig * 2;
                if (r0 < M) {
                    __half2 h = __floats2half2_rn(c[mt][nt][0], c[mt][nt][1]);
                    *(u32*)&dsth[(size_t)r0 * KDIM + col] = *(u32*)&h;
                }
                if (r0 + 8 < M) {
                    __half2 h = __floats2half2_rn(c[mt][nt][2], c[mt][nt][3]);
                    *(u32*)&dsth[(size_t)(r0 + 8) * KDIM + col] = *(u32*)&h;
                }
            }
        }
        return;
    }

    __syncthreads();
#pragma unroll
    for (int mt = 0; mt < 2; mt++) {
        int lr = rowW + mt * 16 + g;
#pragma unroll
        for (int nt = 0; nt < 8; nt++) {
            int col = colW + nt * 8 + tig * 2;
            float2 bv = *(const float2*)&bias[col];
            float o0 = fmaxf(c[mt][nt][0] + bv.x, 0.f);
            float o1 = fmaxf(c[mt][nt][1] + bv.y, 0.f);
            float o2 = fmaxf(c[mt][nt][2] + bv.x, 0.f);
            float o3 = fmaxf(c[mt][nt][3] + bv.y, 0.f);
            __half2 hA = __floats2half2_rn(o0, o1);
            __half2 hB = __floats2half2_rn(o2, o3);
            *(u32*)&As[lr * SPITCH + col] = *(u32*)&hA;
            *(u32*)&As[(lr + 8) * SPITCH + col] = *(u32*)&hB;
        }
    }
    __syncthreads();

    int rowB = wid * 16;
    float d[8][4];
#pragma unroll
    for (int nt = 0; nt < 8; nt++)
#pragma unroll
        for (int p = 0; p < 4; p++) d[nt][p] = 0.f;

#pragma unroll
    for (int ks = 0; ks < 8; ks++) {
        int kb = ks * 16;
        u32 a[4];
        int r0 = rowB + g;
        a[0] = *(const u32*)&As[r0 * SPITCH + kb + tig * 2];
        a[1] = *(const u32*)&As[(r0 + 8) * SPITCH + kb + tig * 2];
        a[2] = *(const u32*)&As[r0 * SPITCH + kb + 8 + tig * 2];
        a[3] = *(const u32*)&As[(r0 + 8) * SPITCH + kb + 8 + tig * 2];
#pragma unroll
        for (int nt = 0; nt < 8; nt++) {
            int n = nt * 8 + g;
            u32 b[2];
            b[0] = *(const u32*)&Wcs[n * SPITCH + kb + tig * 2];
            b[1] = *(const u32*)&Wcs[n * SPITCH + kb + 8 + tig * 2];
            mma16816(d[nt], a, b);
        }
    }

    float* dstf = (float*)dstv;
    int r0 = m0 + rowB + g;
#pragma unroll
    for (int nt = 0; nt < 8; nt++) {
        int col = nt * 8 + tig * 2;
        float2 cv = *(const float2*)&bc[col];
        if (r0 < M) {
            float2 o = make_float2(d[nt][0] + cv.x, d[nt][1] + cv.y);
            *(float2*)&dstf[(size_t)r0 * OUTDIM + col] = o;
        }
        if (r0 + 8 < M) {
            float2 o = make_float2(d[nt][2] + cv.x, d[nt][3] + cv.y);
            *(float2*)&dstf[(size_t)(r0 + 8) * OUTDIM + col] = o;
        }
    }
}

// ---------------- host launch ----------------
extern "C" void kernel_launch(void* const* d_in, const int* in_sizes, int n_in,
                              void* d_out, int out_size) {
    const float* x  = (const float*)d_in[0];
    const int*   ei = (const int*)d_in[1];
    const float* W1 = (const float*)d_in[2];
    const float* b1 = (const float*)d_in[3];
    const float* W2 = (const float*)d_in[4];
    const float* b2 = (const float*)d_in[5];
    const float* W3 = (const float*)d_in[6];
    const float* b3 = (const float*)d_in[7];
    const float* W4 = (const float*)d_in[8];
    const float* b4 = (const float*)d_in[9];
    float* out = (float*)d_out;

    int M = in_sizes[0] / KDIM;         // 50000
    int E = in_sizes[1] / 2;            // 800000
    int NB = 148;                       // 1 resident CTA/SM (co-schedules with gemm1)

    __half *bufH1, *bufH2, *W1t, *W2t, *Wct;
    float *bc;
    cudaGetSymbolAddress((void**)&bufH1, g_bufH1);
    cudaGetSymbolAddress((void**)&bufH2, g_bufH2);
    cudaGetSymbolAddress((void**)&W1t, g_W1t);
    cudaGetSymbolAddress((void**)&W2t, g_W2t);
    cudaGetSymbolAddress((void**)&Wct, g_Wct);
    cudaGetSymbolAddress((void**)&bc, g_bc);

    constexpr int SMEM1 = 2 * 128 * SPITCH * 2;              // 69632 B
    constexpr int SMEM2 = (2 * 128 + 64) * SPITCH * 2;       // 87040 B

    static bool inited = false;
    static cudaStream_t s2;
    static cudaEvent_t evFork, evJoin;
    if (!inited) {
        cudaFuncSetAttribute(gemm_mma_kernel<false, false>,
                             cudaFuncAttributeMaxDynamicSharedMemorySize, SMEM1);
        cudaFuncSetAttribute(gemm_mma_kernel<true, true>,
                             cudaFuncAttributeMaxDynamicSharedMemorySize, SMEM2);
        cudaStreamCreateWithFlags(&s2, cudaStreamNonBlocking);
        cudaEventCreateWithFlags(&evFork, cudaEventDisableTiming);
        cudaEventCreateWithFlags(&evJoin, cudaEventDisableTiming);
        inited = true;
    }

    int spmm_blocks = (M * 32 + 255) / 256;
    int gblocks = (M + 127) / 128;      // 391

    // prep (both must precede csr and gemm1)
    prep_w_kernel<<<256, 128>>>(W1, W2, M);                  // W1t/W2t + zero cnt
    prep_wc_kernel<<<OUTDIM, 128>>>(W3, b3, W4, b4, ei);     // Wct/bc + detect + g_done=0

    // fork: CSR on s2 (enqueued first so its blocks place first), gemm1 on main
    cudaEventRecord(evFork, 0);
    cudaStreamWaitEvent(s2, evFork, 0);
    csr_all_kernel<<<NB, 512, 0, s2>>>(ei, E, M, NB);
    cudaEventRecord(evJoin, s2);

    // g1 = x @ W1 (independent of CSR)
    gemm_mma_kernel<false, false><<<gblocks, 256, SMEM1>>>(x, W1t, nullptr, nullptr,
                                                           nullptr, bufH1, M);
    cudaStreamWaitEvent(0, evJoin, 0);   // join: CSR ready

    // h1 = relu(A*g1 + b1)
    spmm_h_kernel<true, true><<<spmm_blocks, 256>>>(bufH1, b1, bufH2, M);
    // g2 = A*h1
    spmm_h_kernel<false, true><<<spmm_blocks, 256>>>(bufH2, nullptr, bufH1, M);
    // out = relu(g2@W2 + b2)@Wc + bc
    gemm_mma_kernel<true, true><<<gblocks, 256, SMEM2>>>(bufH1, W2t, b2, Wct, bc, out, M);
}